// round 6
// baseline (speedup 1.0000x reference)
#include <cuda_runtime.h>
#include <math.h>

// Problem constants
#define BB 32
#define LL 32768
#define PS 32
#define TT 1024      // L / PS
#define DD 256
#define BT (BB * TT) // 32768 rows

// ---------------- scratch (device globals: sanctioned scratch mechanism) ----
__device__ float g_xn[(size_t)BB * LL];            // 4 MB normalized series
__device__ float g_h[(size_t)BT * DD];             // 32 MB patch embeddings
__device__ float g_qkv[(size_t)BT * 3 * DD];       // 96 MB qkv (row = [q|k|v])
__device__ float g_s[(size_t)BB * TT * TT];        // 128 MB scores / probs
__device__ float g_ao[(size_t)BT * DD];            // 32 MB attn output
__device__ float g_o[(size_t)BT * DD];             // 32 MB out-proj

// ---------------- 1) instance norm (ddof=1, std+1e-5) -----------------------
__global__ void k_norm(const float* __restrict__ x) {
    int b = blockIdx.x;
    const float* xr = x + (size_t)b * LL;
    float* yr = g_xn + (size_t)b * LL;
    float s = 0.f, s2 = 0.f;
    for (int i = threadIdx.x; i < LL; i += blockDim.x) {
        float v = xr[i];
        s += v; s2 += v * v;
    }
    __shared__ float rs[32], rs2[32];
    for (int o = 16; o; o >>= 1) {
        s  += __shfl_xor_sync(0xFFFFFFFFu, s,  o);
        s2 += __shfl_xor_sync(0xFFFFFFFFu, s2, o);
    }
    int w = threadIdx.x >> 5, lane = threadIdx.x & 31;
    if (lane == 0) { rs[w] = s; rs2[w] = s2; }
    __syncthreads();
    __shared__ float sh_mean, sh_inv;
    if (w == 0) {
        s = rs[lane]; s2 = rs2[lane];   // blockDim 1024 -> 32 warps exactly
        for (int o = 16; o; o >>= 1) {
            s  += __shfl_xor_sync(0xFFFFFFFFu, s,  o);
            s2 += __shfl_xor_sync(0xFFFFFFFFu, s2, o);
        }
        if (lane == 0) {
            float mean = s / (float)LL;
            float var = (s2 - s * mean) / (float)(LL - 1);
            sh_mean = mean;
            sh_inv = 1.f / (sqrtf(var) + 1e-5f);
        }
    }
    __syncthreads();
    float mean = sh_mean, inv = sh_inv;
    for (int i = threadIdx.x; i < LL; i += blockDim.x)
        yr[i] = (xr[i] - mean) * inv;
}

// ---------------- 2) patch projection: [BT,32] @ [32,256] + b ---------------
__global__ __launch_bounds__(256) void k_proj(const float* __restrict__ Wp,
                                              const float* __restrict__ bp) {
    __shared__ float sW[PS * DD];   // 32 KB
    __shared__ float sp[32 * PS];   // 32 rows x 32
    int tid = threadIdx.x;
    for (int i = tid; i < PS * DD / 4; i += 256)
        ((float4*)sW)[i] = ((const float4*)Wp)[i];
    int row0 = blockIdx.x * 32;
    ((float4*)sp)[tid] = ((const float4*)(g_xn + (size_t)row0 * PS))[tid];
    __syncthreads();
    int c = tid;
    float acc[32];
#pragma unroll
    for (int r = 0; r < 32; r++) acc[r] = 0.f;
#pragma unroll 8
    for (int k = 0; k < PS; k++) {
        float w = sW[k * DD + c];
#pragma unroll
        for (int r = 0; r < 32; r++) acc[r] += sp[r * PS + k] * w;
    }
    float bias = bp[c];
#pragma unroll
    for (int r = 0; r < 32; r++)
        g_h[(size_t)(row0 + r) * DD + c] = acc[r] + bias;
}

// ---------------- generic 128x128x8 fp32 GEMM (NN) --------------------------
// C[m,n] = sum_k A[m,k]*B[k,n] (+bias[n]).  Batched via blockIdx.z strides.
// causal_klimit: K truncated to m0+128 (valid because P has exact zeros above
// the diagonal after softmax).
__global__ __launch_bounds__(256) void k_gemm_nn(
    const float* __restrict__ A, const float* __restrict__ B,
    const float* __restrict__ bias, float* __restrict__ C,
    int K, int lda, int ldb, int ldc,
    long long sA, long long sB, long long sC, int causal_klimit)
{
    const int m0 = blockIdx.y * 128;
    const int n0 = blockIdx.x * 128;
    A += (long long)blockIdx.z * sA;
    B += (long long)blockIdx.z * sB;
    C += (long long)blockIdx.z * sC;
    int Keff = causal_klimit ? min(K, m0 + 128) : K;

    __shared__ float As[8][128];
    __shared__ float Bs[8][128];
    const int tid = threadIdx.x;
    const int tx = tid & 15, ty = tid >> 4;
    const int arow = tid >> 1, acol = (tid & 1) * 4;
    const int brow = tid >> 5, bcol = (tid & 31) * 4;

    float acc[8][8];
#pragma unroll
    for (int i = 0; i < 8; i++)
#pragma unroll
        for (int j = 0; j < 8; j++) acc[i][j] = 0.f;

    for (int k0 = 0; k0 < Keff; k0 += 8) {
        float4 a = *(const float4*)&A[(long long)(m0 + arow) * lda + k0 + acol];
        As[acol + 0][arow] = a.x;
        As[acol + 1][arow] = a.y;
        As[acol + 2][arow] = a.z;
        As[acol + 3][arow] = a.w;
        *(float4*)&Bs[brow][bcol] =
            *(const float4*)&B[(long long)(k0 + brow) * ldb + n0 + bcol];
        __syncthreads();
#pragma unroll
        for (int k = 0; k < 8; k++) {
            float4 a0 = *(const float4*)&As[k][ty * 8];
            float4 a1 = *(const float4*)&As[k][ty * 8 + 4];
            float4 b0 = *(const float4*)&Bs[k][tx * 8];
            float4 b1 = *(const float4*)&Bs[k][tx * 8 + 4];
            float ar[8] = {a0.x, a0.y, a0.z, a0.w, a1.x, a1.y, a1.z, a1.w};
            float br[8] = {b0.x, b0.y, b0.z, b0.w, b1.x, b1.y, b1.z, b1.w};
#pragma unroll
            for (int i = 0; i < 8; i++)
#pragma unroll
                for (int j = 0; j < 8; j++) acc[i][j] += ar[i] * br[j];
        }
        __syncthreads();
    }
#pragma unroll
    for (int i = 0; i < 8; i++) {
        int m = m0 + ty * 8 + i;
#pragma unroll
        for (int j4 = 0; j4 < 2; j4++) {
            int n = n0 + tx * 8 + j4 * 4;
            float4 v;
            v.x = acc[i][j4 * 4 + 0];
            v.y = acc[i][j4 * 4 + 1];
            v.z = acc[i][j4 * 4 + 2];
            v.w = acc[i][j4 * 4 + 3];
            if (bias) {
                v.x += bias[n]; v.y += bias[n + 1];
                v.z += bias[n + 2]; v.w += bias[n + 3];
            }
            *(float4*)&C[(long long)m * ldc + n] = v;
        }
    }
}

// ---------------- QK^T (NT) with causal tile skip + scale -------------------
__global__ __launch_bounds__(256) void k_gemm_nt(
    const float* __restrict__ A, const float* __restrict__ Bt,
    float* __restrict__ C,
    int K, int lda, int ldb, int ldc,
    long long sA, long long sB, long long sC, float scale)
{
    const int m0 = blockIdx.y * 128;
    const int n0 = blockIdx.x * 128;
    if (n0 > m0 + 127) return;   // fully above the diagonal: never read later
    A  += (long long)blockIdx.z * sA;
    Bt += (long long)blockIdx.z * sB;
    C  += (long long)blockIdx.z * sC;

    __shared__ float As[8][128];
    __shared__ float Bs[8][128];
    const int tid = threadIdx.x;
    const int tx = tid & 15, ty = tid >> 4;
    const int arow = tid >> 1, acol = (tid & 1) * 4;

    float acc[8][8];
#pragma unroll
    for (int i = 0; i < 8; i++)
#pragma unroll
        for (int j = 0; j < 8; j++) acc[i][j] = 0.f;

    for (int k0 = 0; k0 < K; k0 += 8) {
        float4 a = *(const float4*)&A[(long long)(m0 + arow) * lda + k0 + acol];
        As[acol + 0][arow] = a.x;
        As[acol + 1][arow] = a.y;
        As[acol + 2][arow] = a.z;
        As[acol + 3][arow] = a.w;
        float4 b = *(const float4*)&Bt[(long long)(n0 + arow) * ldb + k0 + acol];
        Bs[acol + 0][arow] = b.x;
        Bs[acol + 1][arow] = b.y;
        Bs[acol + 2][arow] = b.z;
        Bs[acol + 3][arow] = b.w;
        __syncthreads();
#pragma unroll
        for (int k = 0; k < 8; k++) {
            float4 a0 = *(const float4*)&As[k][ty * 8];
            float4 a1 = *(const float4*)&As[k][ty * 8 + 4];
            float4 b0 = *(const float4*)&Bs[k][tx * 8];
            float4 b1 = *(const float4*)&Bs[k][tx * 8 + 4];
            float ar[8] = {a0.x, a0.y, a0.z, a0.w, a1.x, a1.y, a1.z, a1.w};
            float br[8] = {b0.x, b0.y, b0.z, b0.w, b1.x, b1.y, b1.z, b1.w};
#pragma unroll
            for (int i = 0; i < 8; i++)
#pragma unroll
                for (int j = 0; j < 8; j++) acc[i][j] += ar[i] * br[j];
        }
        __syncthreads();
    }
#pragma unroll
    for (int i = 0; i < 8; i++) {
        int m = m0 + ty * 8 + i;
#pragma unroll
        for (int j4 = 0; j4 < 2; j4++) {
            int n = n0 + tx * 8 + j4 * 4;
            float4 v;
            v.x = acc[i][j4 * 4 + 0] * scale;
            v.y = acc[i][j4 * 4 + 1] * scale;
            v.z = acc[i][j4 * 4 + 2] * scale;
            v.w = acc[i][j4 * 4 + 3] * scale;
            *(float4*)&C[(long long)m * ldc + n] = v;
        }
    }
}

// ---------------- row softmax over [0, t], zeros above diagonal -------------
__global__ __launch_bounds__(256) void k_softmax(float* __restrict__ S) {
    long long row = blockIdx.x;          // b*1024 + t
    int t = (int)(row & 1023);
    float* p = S + row * TT;
    int n = t + 1;
    int tid = threadIdx.x;
    float mx = -1e30f;
    for (int i = tid; i < n; i += 256) mx = fmaxf(mx, p[i]);
    __shared__ float redm[8], reds[8];
    for (int o = 16; o; o >>= 1) mx = fmaxf(mx, __shfl_xor_sync(0xFFFFFFFFu, mx, o));
    if ((tid & 31) == 0) redm[tid >> 5] = mx;
    __syncthreads();
    mx = redm[0];
#pragma unroll
    for (int w = 1; w < 8; w++) mx = fmaxf(mx, redm[w]);

    float s = 0.f;
    for (int i = tid; i < TT; i += 256) {
        float e = (i < n) ? __expf(p[i] - mx) : 0.f;
        p[i] = e;
        s += e;
    }
    for (int o = 16; o; o >>= 1) s += __shfl_xor_sync(0xFFFFFFFFu, s, o);
    if ((tid & 31) == 0) reds[tid >> 5] = s;
    __syncthreads();
    s = reds[0];
#pragma unroll
    for (int w = 1; w < 8; w++) s += reds[w];
    float r = 1.f / s;
    for (int i = tid; i < n; i += 256) p[i] *= r;
}

// ---------------- zero loss accumulator -------------------------------------
__global__ void k_zero(float* out) { out[0] = 0.f; }

// ---------------- head GEMM + next-patch MSE (fused) ------------------------
__global__ __launch_bounds__(128) void k_head_loss(
    const float* __restrict__ Wh, const float* __restrict__ bh,
    float* __restrict__ out)
{
    const float INV_COUNT = 1.f / (float)(BB * (TT - 1) * PS);
    int r = blockIdx.x;                 // 0 .. 32*1023-1
    int b = r / (TT - 1), t = r % (TT - 1);
    const float* orow = g_o + ((long long)b * TT + t) * DD;
    __shared__ float so[DD];
    __shared__ float sp[4][32];
    int tid = threadIdx.x;
    so[tid] = orow[tid];
    so[tid + 128] = orow[tid + 128];
    __syncthreads();
    int j = tid & 31, kq = tid >> 5;
    float a = 0.f;
#pragma unroll 16
    for (int k = kq * 64; k < kq * 64 + 64; k++)
        a += so[k] * Wh[k * PS + j];
    sp[kq][j] = a;
    __syncthreads();
    if (tid < 32) {
        float pred = sp[0][j] + sp[1][j] + sp[2][j] + sp[3][j] + bh[j];
        float tgt = g_xn[(long long)b * LL + (long long)(t + 1) * PS + j];
        float d = pred - tgt;
        float sq = d * d;
        for (int o = 16; o; o >>= 1) sq += __shfl_xor_sync(0xFFFFFFFFu, sq, o);
        if (j == 0) atomicAdd(out, sq * INV_COUNT);
    }
}

// ---------------- launch ----------------------------------------------------
extern "C" void kernel_launch(void* const* d_in, const int* in_sizes, int n_in,
                              void* d_out, int out_size) {
    (void)in_sizes; (void)n_in; (void)out_size;
    const float* x      = (const float*)d_in[0];
    const float* W_proj = (const float*)d_in[1];
    const float* b_proj = (const float*)d_in[2];
    const float* W_qkv  = (const float*)d_in[3];
    const float* b_qkv  = (const float*)d_in[4];
    const float* W_out  = (const float*)d_in[5];
    const float* b_out  = (const float*)d_in[6];
    const float* W_head = (const float*)d_in[7];
    const float* b_head = (const float*)d_in[8];
    float* out = (float*)d_out;

    float *p_h, *p_qkv, *p_s, *p_ao, *p_o;
    cudaGetSymbolAddress((void**)&p_h,   g_h);
    cudaGetSymbolAddress((void**)&p_qkv, g_qkv);
    cudaGetSymbolAddress((void**)&p_s,   g_s);
    cudaGetSymbolAddress((void**)&p_ao,  g_ao);
    cudaGetSymbolAddress((void**)&p_o,   g_o);

    // 1) instance norm
    k_norm<<<BB, 1024>>>(x);
    // 2) patch embedding: g_h = patches @ W_proj + b
    k_proj<<<BT / 32, 256>>>(W_proj, b_proj);
    // 3) qkv = h @ W_qkv + b : [32768,256]@[256,768]
    k_gemm_nn<<<dim3(3 * DD / 128, BT / 128, 1), 256>>>(
        p_h, W_qkv, b_qkv, p_qkv, DD, DD, 3 * DD, 3 * DD, 0, 0, 0, 0);
    // 4) S = scale * q @ k^T  (causal tiles only), per batch
    k_gemm_nt<<<dim3(TT / 128, TT / 128, BB), 256>>>(
        p_qkv, p_qkv + DD, p_s, DD, 3 * DD, 3 * DD, TT,
        (long long)TT * 3 * DD, (long long)TT * 3 * DD, (long long)TT * TT,
        0.0625f);
    // 5) causal softmax (writes exact zeros above diagonal)
    k_softmax<<<BT, 256>>>(p_s);
    // 6) attn_out = P @ v  (K truncated by causal structure)
    k_gemm_nn<<<dim3(DD / 128, TT / 128, BB), 256>>>(
        p_s, p_qkv + 2 * DD, nullptr, p_ao, TT, TT, 3 * DD, DD,
        (long long)TT * TT, (long long)TT * 3 * DD, (long long)TT * DD, 1);
    // 7) out = attn_out @ W_out + b
    k_gemm_nn<<<dim3(DD / 128, BT / 128, 1), 256>>>(
        p_ao, W_out, b_out, p_o, DD, DD, DD, DD, 0, 0, 0, 0);
    // 8) loss
    k_zero<<<1, 1>>>(out);
    k_head_loss<<<BB * (TT - 1), 128>>>(W_head, b_head, out);
}

// round 11
// speedup vs baseline: 2.4975x; 2.4975x over previous
#include <cuda_runtime.h>
#include <math.h>
#include <stdint.h>

// Problem constants
#define BB 32
#define LL 32768
#define PS 32
#define TT 1024      // L / PS
#define DD 256
#define BT (BB * TT) // 32768 rows

// ---------------- scratch (device globals: sanctioned scratch mechanism) ----
__device__ float g_xn[(size_t)BB * LL];            // 4 MB normalized series
__device__ float g_h[(size_t)BT * DD];             // 32 MB patch embeddings
__device__ float g_qkv[(size_t)BT * 3 * DD];       // 96 MB qkv (row = [q|k|v])
__device__ float g_s[(size_t)BB * TT * TT];        // 128 MB scores / probs
__device__ float g_ao[(size_t)BT * DD];            // 32 MB attn output
__device__ float g_o[(size_t)BT * DD];             // 32 MB out-proj

// ---------------- helpers ----------------------------------------------------
__device__ __forceinline__ uint32_t f2tf(float f) {
    uint32_t u;
    asm("cvt.rna.tf32.f32 %0, %1;" : "=r"(u) : "f"(f));
    return u;
}
__device__ __forceinline__ void mma8(float* c, const uint32_t* a, const uint32_t* b) {
    asm volatile(
        "mma.sync.aligned.m16n8k8.row.col.f32.tf32.tf32.f32 "
        "{%0,%1,%2,%3}, {%4,%5,%6,%7}, {%8,%9}, {%0,%1,%2,%3};"
        : "+f"(c[0]), "+f"(c[1]), "+f"(c[2]), "+f"(c[3])
        : "r"(a[0]), "r"(a[1]), "r"(a[2]), "r"(a[3]), "r"(b[0]), "r"(b[1]));
}

// ---------------- 1) instance norm (ddof=1, std+1e-5) -----------------------
__global__ void k_norm(const float* __restrict__ x) {
    int b = blockIdx.x;
    const float* xr = x + (size_t)b * LL;
    float* yr = g_xn + (size_t)b * LL;
    float s = 0.f, s2 = 0.f;
    for (int i = threadIdx.x; i < LL; i += blockDim.x) {
        float v = xr[i];
        s += v; s2 += v * v;
    }
    __shared__ float rs[32], rs2[32];
    for (int o = 16; o; o >>= 1) {
        s  += __shfl_xor_sync(0xFFFFFFFFu, s,  o);
        s2 += __shfl_xor_sync(0xFFFFFFFFu, s2, o);
    }
    int w = threadIdx.x >> 5, lane = threadIdx.x & 31;
    if (lane == 0) { rs[w] = s; rs2[w] = s2; }
    __syncthreads();
    __shared__ float sh_mean, sh_inv;
    if (w == 0) {
        s = rs[lane]; s2 = rs2[lane];   // blockDim 1024 -> 32 warps exactly
        for (int o = 16; o; o >>= 1) {
            s  += __shfl_xor_sync(0xFFFFFFFFu, s,  o);
            s2 += __shfl_xor_sync(0xFFFFFFFFu, s2, o);
        }
        if (lane == 0) {
            float mean = s / (float)LL;
            float var = (s2 - s * mean) / (float)(LL - 1);
            sh_mean = mean;
            sh_inv = 1.f / (sqrtf(var) + 1e-5f);
        }
    }
    __syncthreads();
    float mean = sh_mean, inv = sh_inv;
    for (int i = threadIdx.x; i < LL; i += blockDim.x)
        yr[i] = (xr[i] - mean) * inv;
}

// ---------------- 2) patch projection: [BT,32] @ [32,256] + b ---------------
__global__ __launch_bounds__(256) void k_proj(const float* __restrict__ Wp,
                                              const float* __restrict__ bp) {
    __shared__ float sW[PS * DD];   // 32 KB
    __shared__ float sp[32 * PS];   // 32 rows x 32
    int tid = threadIdx.x;
    for (int i = tid; i < PS * DD / 4; i += 256)
        ((float4*)sW)[i] = ((const float4*)Wp)[i];
    int row0 = blockIdx.x * 32;
    ((float4*)sp)[tid] = ((const float4*)(g_xn + (size_t)row0 * PS))[tid];
    __syncthreads();
    int c = tid;
    float acc[32];
#pragma unroll
    for (int r = 0; r < 32; r++) acc[r] = 0.f;
#pragma unroll 8
    for (int k = 0; k < PS; k++) {
        float w = sW[k * DD + c];
#pragma unroll
        for (int r = 0; r < 32; r++) acc[r] += sp[r * PS + k] * w;
    }
    float bias = bp[c];
#pragma unroll
    for (int r = 0; r < 32; r++)
        g_h[(size_t)(row0 + r) * DD + c] = acc[r] + bias;
}

// ---------------- tf32 tensor-core GEMM, 128x128x32 tiles -------------------
// C = (A @ op(B)) * scale + bias.  TRANSB=0: B is [K][N]; TRANSB=1: B is [N][K].
// CAUSAL=1: skip tiles fully above the diagonal (QK^T).
// CAUSAL=2: truncate K to m0+128 (P @ V with exact zeros above diagonal).
// Smem layouts (word strides) chosen conflict-free:
//   A tile  [m][k] stride 36:  STS.128 fill and frag LDS both hit 32 distinct banks
//   NT B    [n][k] stride 36:  same as A (transpose folded into frag indexing)
//   NN B    [k][n] stride 136: (8k+n) mod 32 unique across the warp
template <int TRANSB, int CAUSAL>
__global__ __launch_bounds__(256) void k_mma(
    const float* __restrict__ A, const float* __restrict__ B,
    const float* __restrict__ bias, float* __restrict__ C,
    int K, int lda, int ldb, int ldc,
    long long sA, long long sB, long long sC, float scale)
{
    const int m0 = blockIdx.y * 128;
    const int n0 = blockIdx.x * 128;
    if (CAUSAL == 1 && n0 > m0 + 127) return;
    A += (long long)blockIdx.z * sA;
    B += (long long)blockIdx.z * sB;
    C += (long long)blockIdx.z * sC;
    const int Keff = (CAUSAL == 2) ? min(K, m0 + 128) : K;

    __shared__ uint32_t As[128 * 36];                       // 18432 B
    __shared__ uint32_t Bs[TRANSB ? 128 * 36 : 32 * 136];   // <= 18432 B

    const int tid = threadIdx.x;
    const int lane = tid & 31;
    const int wid = tid >> 5;
    const int wm = (wid >> 2) * 64;   // warp M offset (2 rows of warps)
    const int wn = (wid & 3) * 32;    // warp N offset (4 cols of warps)

    float c[4][4][4];
#pragma unroll
    for (int i = 0; i < 4; i++)
#pragma unroll
        for (int j = 0; j < 4; j++)
#pragma unroll
            for (int r = 0; r < 4; r++) c[i][j][r] = 0.f;

    const int ar = tid >> 3;        // 0..31 (+32*i)
    const int ac = (tid & 7) * 4;   // 0..28

    for (int k0 = 0; k0 < Keff; k0 += 32) {
        // ---- fill A tile [128][32] ----
#pragma unroll
        for (int i = 0; i < 4; i++) {
            float4 v = *(const float4*)&A[(long long)(m0 + ar + 32 * i) * lda + k0 + ac];
            uint4 t = {f2tf(v.x), f2tf(v.y), f2tf(v.z), f2tf(v.w)};
            *(uint4*)&As[(ar + 32 * i) * 36 + ac] = t;
        }
        // ---- fill B tile ----
        if (TRANSB) {
            // B global [N][K]; store A-style [n][k] stride 36
#pragma unroll
            for (int i = 0; i < 4; i++) {
                float4 v = *(const float4*)&B[(long long)(n0 + ar + 32 * i) * ldb + k0 + ac];
                uint4 t = {f2tf(v.x), f2tf(v.y), f2tf(v.z), f2tf(v.w)};
                *(uint4*)&Bs[(ar + 32 * i) * 36 + ac] = t;
            }
        } else {
            // B global [K][N]; store [k][n] stride 136
            const int br = tid >> 5;          // 0..7 (+8*i)
            const int bc = (tid & 31) * 4;    // 0..124
#pragma unroll
            for (int i = 0; i < 4; i++) {
                float4 v = *(const float4*)&B[(long long)(k0 + br + 8 * i) * ldb + n0 + bc];
                uint4 t = {f2tf(v.x), f2tf(v.y), f2tf(v.z), f2tf(v.w)};
                *(uint4*)&Bs[(br + 8 * i) * 136 + bc] = t;
            }
        }
        __syncthreads();

        // ---- 4 k-steps of m16n8k8 ----
#pragma unroll
        for (int ks = 0; ks < 4; ks++) {
            uint32_t a[4][4], b[4][2];
            const int am = wm + (lane >> 2);
            const int ak = ks * 8 + (lane & 3);
#pragma unroll
            for (int mi = 0; mi < 4; mi++) {
                a[mi][0] = As[(am + mi * 16)     * 36 + ak];
                a[mi][1] = As[(am + mi * 16 + 8) * 36 + ak];
                a[mi][2] = As[(am + mi * 16)     * 36 + ak + 4];
                a[mi][3] = As[(am + mi * 16 + 8) * 36 + ak + 4];
            }
            const int bk = ks * 8 + (lane & 3);
            const int bn = wn + (lane >> 2);
#pragma unroll
            for (int ni = 0; ni < 4; ni++) {
                if (TRANSB) {
                    b[ni][0] = Bs[(bn + ni * 8) * 36 + bk];
                    b[ni][1] = Bs[(bn + ni * 8) * 36 + bk + 4];
                } else {
                    b[ni][0] = Bs[bk       * 136 + bn + ni * 8];
                    b[ni][1] = Bs[(bk + 4) * 136 + bn + ni * 8];
                }
            }
#pragma unroll
            for (int mi = 0; mi < 4; mi++)
#pragma unroll
                for (int ni = 0; ni < 4; ni++)
                    mma8(c[mi][ni], a[mi], b[ni]);
        }
        __syncthreads();
    }

    // ---- epilogue ----
#pragma unroll
    for (int mi = 0; mi < 4; mi++) {
        const int r0 = m0 + wm + mi * 16 + (lane >> 2);
#pragma unroll
        for (int ni = 0; ni < 4; ni++) {
            const int cc = n0 + wn + ni * 8 + (lane & 3) * 2;
            float2 v0, v1;
            v0.x = c[mi][ni][0] * scale;
            v0.y = c[mi][ni][1] * scale;
            v1.x = c[mi][ni][2] * scale;
            v1.y = c[mi][ni][3] * scale;
            if (bias) {
                float2 bb = *(const float2*)&bias[cc];
                v0.x += bb.x; v0.y += bb.y;
                v1.x += bb.x; v1.y += bb.y;
            }
            *(float2*)&C[(long long)r0 * ldc + cc] = v0;
            *(float2*)&C[(long long)(r0 + 8) * ldc + cc] = v1;
        }
    }
}

// ---------------- row softmax over [0, t], zeros up to 128-block end --------
__global__ __launch_bounds__(256) void k_softmax(float* __restrict__ S) {
    long long row = blockIdx.x;          // b*1024 + t
    int t = (int)(row & 1023);
    float* p = S + row * TT;
    int n = t + 1;
    int n_pad = ((t >> 7) + 1) << 7;     // only cols < n_pad are ever read by PV
    int tid = threadIdx.x;
    float mx = -1e30f;
    for (int i = tid; i < n; i += 256) mx = fmaxf(mx, p[i]);
    __shared__ float redm[8], reds[8];
    for (int o = 16; o; o >>= 1) mx = fmaxf(mx, __shfl_xor_sync(0xFFFFFFFFu, mx, o));
    if ((tid & 31) == 0) redm[tid >> 5] = mx;
    __syncthreads();
    mx = redm[0];
#pragma unroll
    for (int w = 1; w < 8; w++) mx = fmaxf(mx, redm[w]);

    float s = 0.f;
    for (int i = tid; i < n_pad; i += 256) {
        float e = (i < n) ? __expf(p[i] - mx) : 0.f;
        p[i] = e;
        s += e;
    }
    for (int o = 16; o; o >>= 1) s += __shfl_xor_sync(0xFFFFFFFFu, s, o);
    if ((tid & 31) == 0) reds[tid >> 5] = s;
    __syncthreads();
    s = reds[0];
#pragma unroll
    for (int w = 1; w < 8; w++) s += reds[w];
    float r = 1.f / s;
    for (int i = tid; i < n; i += 256) p[i] *= r;
}

// ---------------- zero loss accumulator -------------------------------------
__global__ void k_zero(float* out) { out[0] = 0.f; }

// ---------------- head GEMM + next-patch MSE (fused) ------------------------
__global__ __launch_bounds__(128) void k_head_loss(
    const float* __restrict__ Wh, const float* __restrict__ bh,
    float* __restrict__ out)
{
    const float INV_COUNT = 1.f / (float)(BB * (TT - 1) * PS);
    int r = blockIdx.x;                 // 0 .. 32*1023-1
    int b = r / (TT - 1), t = r % (TT - 1);
    const float* orow = g_o + ((long long)b * TT + t) * DD;
    __shared__ float so[DD];
    __shared__ float sp[4][32];
    int tid = threadIdx.x;
    so[tid] = orow[tid];
    so[tid + 128] = orow[tid + 128];
    __syncthreads();
    int j = tid & 31, kq = tid >> 5;
    float a = 0.f;
#pragma unroll 16
    for (int k = kq * 64; k < kq * 64 + 64; k++)
        a += so[k] * Wh[k * PS + j];
    sp[kq][j] = a;
    __syncthreads();
    if (tid < 32) {
        float pred = sp[0][j] + sp[1][j] + sp[2][j] + sp[3][j] + bh[j];
        float tgt = g_xn[(long long)b * LL + (long long)(t + 1) * PS + j];
        float d = pred - tgt;
        float sq = d * d;
        for (int o = 16; o; o >>= 1) sq += __shfl_xor_sync(0xFFFFFFFFu, sq, o);
        if (j == 0) atomicAdd(out, sq * INV_COUNT);
    }
}

// ---------------- launch ----------------------------------------------------
extern "C" void kernel_launch(void* const* d_in, const int* in_sizes, int n_in,
                              void* d_out, int out_size) {
    (void)in_sizes; (void)n_in; (void)out_size;
    const float* x      = (const float*)d_in[0];
    const float* W_proj = (const float*)d_in[1];
    const float* b_proj = (const float*)d_in[2];
    const float* W_qkv  = (const float*)d_in[3];
    const float* b_qkv  = (const float*)d_in[4];
    const float* W_out  = (const float*)d_in[5];
    const float* b_out  = (const float*)d_in[6];
    const float* W_head = (const float*)d_in[7];
    const float* b_head = (const float*)d_in[8];
    float* out = (float*)d_out;

    float *p_h, *p_qkv, *p_s, *p_ao, *p_o;
    cudaGetSymbolAddress((void**)&p_h,   g_h);
    cudaGetSymbolAddress((void**)&p_qkv, g_qkv);
    cudaGetSymbolAddress((void**)&p_s,   g_s);
    cudaGetSymbolAddress((void**)&p_ao,  g_ao);
    cudaGetSymbolAddress((void**)&p_o,   g_o);

    // 1) instance norm
    k_norm<<<BB, 1024>>>(x);
    // 2) patch embedding: g_h = patches @ W_proj + b
    k_proj<<<BT / 32, 256>>>(W_proj, b_proj);
    // 3) qkv = h @ W_qkv + b : [32768,256]@[256,768]   (tf32 MMA)
    k_mma<0, 0><<<dim3(3 * DD / 128, BT / 128, 1), 256>>>(
        p_h, W_qkv, b_qkv, p_qkv, DD, DD, 3 * DD, 3 * DD, 0, 0, 0, 1.f);
    // 4) S = scale * q @ k^T  (causal tiles only), per batch  (tf32 MMA, NT)
    k_mma<1, 1><<<dim3(TT / 128, TT / 128, BB), 256>>>(
        p_qkv, p_qkv + DD, nullptr, p_s, DD, 3 * DD, 3 * DD, TT,
        (long long)TT * 3 * DD, (long long)TT * 3 * DD, (long long)TT * TT,
        0.0625f);
    // 5) causal softmax (exact zeros up to the 128-block boundary)
    k_softmax<<<BT, 256>>>(p_s);
    // 6) attn_out = P @ v  (K truncated by causal structure)  (tf32 MMA)
    k_mma<0, 2><<<dim3(DD / 128, TT / 128, BB), 256>>>(
        p_s, p_qkv + 2 * DD, nullptr, p_ao, TT, TT, 3 * DD, DD,
        (long long)TT * TT, (long long)TT * 3 * DD, (long long)TT * DD, 1.f);
    // 7) out = attn_out @ W_out + b   (tf32 MMA)
    k_mma<0, 0><<<dim3(DD / 128, BT / 128, 1), 256>>>(
        p_ao, W_out, b_out, p_o, DD, DD, DD, DD, 0, 0, 0, 1.f);
    // 8) loss
    k_zero<<<1, 1>>>(out);
    k_head_loss<<<BB * (TT - 1), 128>>>(W_head, b_head, out);
}